// round 15
// baseline (speedup 1.0000x reference)
#include <cuda_runtime.h>
#include <cuda_bf16.h>

#define Bn 8
#define Dn 1024
#define Gn 32
#define Kn 64
#define NPn 1024
#define NTILE 128
#define GRID 592      // 148 SMs * 4 CTA/SM, one wave

// Scratch (device globals; no allocation allowed)
__device__ unsigned int g_zh[(size_t)Bn * Dn * NPn / 2]; // z bf16 hi, [b][d][n] pairs
__device__ unsigned int g_zl[(size_t)Bn * Dn * NPn / 2]; // z bf16 lo (residual)
__device__ float        g_cw[Bn * Gn * Kn];              // coeff*mask*weight
__device__ unsigned int g_RT[2 * 2048];                  // R^T bf16 hi|lo, SW128-preswizzled
__device__ int          g_items[Bn * Gn];
__device__ int          g_nitems;

#define SWZ(o) ((o) ^ (((o) >> 3) & 0x70))

// pack two f32 -> bf16x2 (lo half = first arg), round-to-nearest
#define CVT2(res, lo, hi) \
    asm("cvt.rn.bf16x2.f32 %0, %1, %2;" : "=r"(res) : "f"(hi), "f"(lo))

#define CP_ASYNC16(dst_s32, src_g) \
    asm volatile("cp.async.cg.shared.global [%0], [%1], 16;" \
                 :: "r"(dst_s32), "l"(src_g))
#define CP_COMMIT() asm volatile("cp.async.commit_group;")
#define CP_WAIT0()  asm volatile("cp.async.wait_group 0;")

__device__ __forceinline__ unsigned int smem_u32(const void* p) {
    unsigned int a;
    asm("{ .reg .u64 t; cvta.to.shared.u64 t, %1; cvt.u32.u64 %0, t; }"
        : "=r"(a) : "l"(p));
    return a;
}

#define LDSM4(r, addr) \
    asm volatile("ldmatrix.sync.aligned.m8n8.x4.shared.b16 {%0,%1,%2,%3}, [%4];" \
        : "=r"((r)[0]), "=r"((r)[1]), "=r"((r)[2]), "=r"((r)[3]) : "r"(addr))
#define LDSM4T(r, addr) \
    asm volatile("ldmatrix.sync.aligned.m8n8.x4.trans.shared.b16 {%0,%1,%2,%3}, [%4];" \
        : "=r"((r)[0]), "=r"((r)[1]), "=r"((r)[2]), "=r"((r)[3]) : "r"(addr))

#define MMA16816(d, a, b0, b1) \
    asm volatile("mma.sync.aligned.m16n8k16.row.col.f32.bf16.bf16.f32 " \
        "{%0,%1,%2,%3}, {%4,%5,%6,%7}, {%8,%9}, {%0,%1,%2,%3};" \
        : "+f"((d)[0]), "+f"((d)[1]), "+f"((d)[2]), "+f"((d)[3]) \
        : "r"((a)[0]), "r"((a)[1]), "r"((a)[2]), "r"((a)[3]), \
          "r"(b0), "r"(b1))

// smem layout (dynamic; bases 1024-aligned for the swizzles)
#define SB1   0         // B r1: 64 x 64 bf16 (8 KB), SW128-preswizzled
#define SB2   8192      // B r2
#define SA    16384     // A bufs: 2 x (hi 8KB + lo 8KB), k-major 256B rows
#define SCW   49152     // 64 floats
#define SMEMB 49408

// ---------------------------------------------------------------------------
// Kernel 1 (prep): transpose + bf16 hi/lo split of z + cw + work list + R^T.
// ---------------------------------------------------------------------------
__global__ void prep_kernel(const float* __restrict__ x,
                            const float* __restrict__ xopt,
                            const int*   __restrict__ gc,
                            const void*  __restrict__ vm,
                            const float* __restrict__ w,
                            const float* __restrict__ R,
                            float*       __restrict__ out)
{
    __shared__ float t[32][33];     // [n_local][d_local]
    int b  = blockIdx.z;
    int n0 = blockIdx.x * 32;
    int d0 = blockIdx.y * 32;
    int tx = threadIdx.x, ty = threadIdx.y;
    int tid = ty * 32 + tx;

    #pragma unroll
    for (int j = ty; j < 32; j += 8) {
        int n = n0 + j, d = d0 + tx;
        t[j][tx] = x[((size_t)b * NPn + n) * Dn + d] - xopt[b * Dn + d];
    }
    __syncthreads();

    // write split bf16 planes: 16 lanes per d-row, each packs an n-pair
    #pragma unroll
    for (int it = 0; it < 2; ++it) {
        int dr = (tid >> 4) + it * 16;      // d_local 0..31
        int p  = tid & 15;                  // n-pair index
        float v0 = t[2 * p][dr];
        float v1 = t[2 * p + 1][dr];
        unsigned int hp; CVT2(hp, v0, v1);
        float v0r = v0 - __uint_as_float(hp << 16);
        float v1r = v1 - __uint_as_float(hp & 0xffff0000u);
        unsigned int lp; CVT2(lp, v0r, v1r);
        size_t o = (size_t)(b * Dn + d0 + dr) * (NPn / 2) + (n0 >> 1) + p;
        g_zh[o] = hp;
        g_zl[o] = lp;
    }

    if (blockIdx.x == 0 && blockIdx.y == 0) {
        int mode4 = 1;
        #pragma unroll
        for (int i = 0; i < 16; ++i) {
            unsigned int v = __ldg((const unsigned int*)vm + i);
            if (v != 0u && v != 1u && v != 0x3F800000u) mode4 = 0;
        }
        int gcb = gc[b];
        for (int i = tid; i < Gn * Kn; i += 256) {
            int g = i >> 6, k = i & 63;
            int gi = b * Gn * Kn + i;
            bool m;
            if (mode4) m = (((const unsigned int*)vm)[gi] != 0u);
            else       m = (((const unsigned char*)vm)[gi] != 0);
            float cf = exp2f((float)k * (19.931568569324174f / 63.0f));
            float wv = (g < gcb) ? w[b * Gn + g] : 0.0f;
            g_cw[gi] = m ? cf * wv : 0.0f;
        }
        for (int i = tid; i < NPn; i += 256) out[b * NPn + i] = 0.0f;

        if (b == 0) {
            if (tid == 0) {
                int mcnt = 0;
                for (int bb = 0; bb < Bn; ++bb) {
                    int c = gc[bb];
                    for (int g = 0; g < c; ++g) g_items[mcnt++] = (bb << 8) | g;
                }
                g_nitems = mcnt;
            }
            // R^T bf16 hi/lo split, SW128-pre-swizzled rows of 128 B (row = l)
            for (int i = tid; i < 2048; i += 256) {
                int l = i >> 5, p = i & 31, k0 = 2 * p;
                float v0 = R[k0 * Kn + l];
                float v1 = R[(k0 + 1) * Kn + l];
                unsigned int r1p; CVT2(r1p, v0, v1);
                float v0r = v0 - __uint_as_float(r1p << 16);
                float v1r = v1 - __uint_as_float(r1p & 0xffff0000u);
                unsigned int r2p; CVT2(r2p, v0r, v1r);
                int off = l * 128 + 4 * p;
                int sw  = SWZ(off) >> 2;
                g_RT[sw]        = r1p;
                g_RT[2048 + sw] = r2p;
            }
        }
    }
}

// ---------------------------------------------------------------------------
// Kernel 2: fitness via mma.sync bf16. Grid GRID=592 (one wave), block 256.
// Unit = ((b,g) item, 128-n tile); stage = 32-k half. cp.async gathers the
// pre-split bf16 A tile k-major (256B rows, ^((k&7)<<4) swizzle), double-
// buffered, one barrier per stage. A frags via ldmatrix.x4.trans, B via
// LDSM4 (two l-tiles per load). D = z1r1 + z1r2 + z2r1, fp32 reg accum.
// ---------------------------------------------------------------------------
__global__ __launch_bounds__(256, 4) void fitness_kernel(
    const int* __restrict__ gidx,
    float*     __restrict__ out)
{
    extern __shared__ char sm[];
    unsigned int smb = smem_u32(sm);
    int tid  = threadIdx.x;
    int wid  = tid >> 5;
    int lane = tid & 31;
    int cta  = blockIdx.x;

    int nunits = 8 * g_nitems;
    int mu = (cta < nunits) ? ((nunits - 1 - cta) / GRID + 1) : 0;
    if (mu == 0) return;
    int ts = 2 * mu;

    float* cw_s = (float*)(sm + SCW);

    // B tiles (r1|r2, 16 KB, pre-swizzled) -> smem once (lands with stage 0)
    {
        const char* src = (const char*)g_RT;
        for (int i = tid; i < 1024; i += 256)
            CP_ASYNC16(smb + SB1 + i * 16, src + i * 16);
    }

    // ---- per-lane ldmatrix address components ----
    int L8   = lane & 7;
    int tsel = lane >> 3;
    // A (trans, k-major rows of 256B): tile r0=(m0-7,k0-7) r1=(m8-15,k0-7)
    //                                  r2=(m0-7,k8-15) r3=(m8-15,k8-15)
    int a_kin  = L8 + ((tsel >> 1) << 3);              // k row within kstep
    int a_nseg = wid * 16 + ((tsel & 1) << 3);         // n segment
    unsigned int aoff = (unsigned)a_kin * 256 +
                        (((unsigned)(a_nseg * 2)) ^ ((unsigned)L8 << 4));
    // B (non-trans, l-major rows of 128B): r0,r1 = lt_even (k0-7 | k8-15),
    //                                      r2,r3 = lt_odd
    int b_kh  = (lane >> 3) & 1;                       // +8 k
    int b_lth = lane >> 4;                             // l tile within pair
    unsigned int b_row = (unsigned)(b_lth * 8 + L8) * 128;
    unsigned int b_kb0 = (unsigned)(b_kh * 16);
    unsigned int b_xor = (unsigned)L8 << 4;

    // gather: thread owns k_local = tid>>3 (0..31), 32B n-chunk (tid&7)
    int kq = tid >> 3;
    int c8 = tid & 7;
    unsigned int asw = ((unsigned)(c8 * 32)) ^ (((unsigned)kq & 7) << 4);
    unsigned int asw1 = ((unsigned)(c8 * 32 + 16)) ^ (((unsigned)kq & 7) << 4);

    // stage j: unit = cta + (j>>1)*GRID, k-half h = j&1
    #define ISSUE(j)                                                           \
    {                                                                          \
        int u_  = cta + ((j) >> 1) * GRID;                                     \
        int it_ = g_items[u_ >> 3];                                            \
        int b_  = it_ >> 8, g_ = it_ & 255, n0_ = (u_ & 7) * NTILE;            \
        int col_ = __ldg(gidx + (b_ * Gn + g_) * Kn + ((j) & 1) * 32 + kq);    \
        size_t so_ = ((size_t)(b_ * Dn + col_) * NPn + n0_) * 2 + c8 * 32;     \
        unsigned int ab_ = smb + SA + ((j) & 1) * 16384 + kq * 256;            \
        CP_ASYNC16(ab_ + asw,         (const char*)g_zh + so_);                \
        CP_ASYNC16(ab_ + asw1,        (const char*)g_zh + so_ + 16);           \
        CP_ASYNC16(ab_ + 8192 + asw,  (const char*)g_zl + so_);                \
        CP_ASYNC16(ab_ + 8192 + asw1, (const char*)g_zl + so_ + 16);           \
        CP_COMMIT();                                                           \
    }

    float d[8][4];
    int ub = 0, un0 = 0, ug = 0;

    ISSUE(0);

    for (int j = 0; j < ts; ++j) {
        int h = j & 1;

        CP_WAIT0();          // stage j (and B, on j=0) landed
        __syncthreads();     // visible to all; all past compute(j-1)
        if (j + 1 < ts) ISSUE(j + 1);

        if (h == 0) {
            int u  = cta + (j >> 1) * GRID;
            int it = g_items[u >> 3];
            ub = it >> 8; ug = it & 255; un0 = (u & 7) * NTILE;
            if (tid < Kn)
                cw_s[tid] = __ldg(g_cw + (ub * Gn + ug) * Kn + tid);
            #pragma unroll
            for (int lt = 0; lt < 8; ++lt)
                #pragma unroll
                for (int q = 0; q < 4; ++q) d[lt][q] = 0.0f;
        }

        unsigned int abuf = smb + SA + (unsigned)h * 16384;
        unsigned int hk64 = (unsigned)h * 64;

        #pragma unroll
        for (int ks = 0; ks < 2; ++ks) {
            unsigned int ah[4], al[4];
            LDSM4T(ah, abuf + ks * 4096 + aoff);
            LDSM4T(al, abuf + 8192 + ks * 4096 + aoff);
            unsigned int bko = (hk64 + (unsigned)(ks * 32) + b_kb0) ^ b_xor;
            #pragma unroll
            for (int lp = 0; lp < 4; ++lp) {
                unsigned int bh[4], bl[4];
                unsigned int bb = (unsigned)lp * 2048 + b_row + bko;
                LDSM4(bh, smb + SB1 + bb);
                LDSM4(bl, smb + SB2 + bb);
                MMA16816(d[lp * 2],     ah, bh[0], bh[1]);
                MMA16816(d[lp * 2],     ah, bl[0], bl[1]);
                MMA16816(d[lp * 2],     al, bh[0], bh[1]);
                MMA16816(d[lp * 2 + 1], ah, bh[2], bh[3]);
                MMA16816(d[lp * 2 + 1], ah, bl[2], bl[3]);
                MMA16816(d[lp * 2 + 1], al, bh[2], bh[3]);
            }
        }

        if (h == 1) {
            // epilogue: D rows wid*16 + lane>>2 (+8); cols lt*8+(lane&3)*2+{0,1}
            float fs0 = 0.0f, fs1 = 0.0f;
            #pragma unroll
            for (int lt = 0; lt < 8; ++lt) {
                int c0 = lt * 8 + (lane & 3) * 2;
                float cw0 = cw_s[c0], cw1 = cw_s[c0 + 1];
                fs0 += cw0 * d[lt][0] * d[lt][0] + cw1 * d[lt][1] * d[lt][1];
                fs1 += cw0 * d[lt][2] * d[lt][2] + cw1 * d[lt][3] * d[lt][3];
            }
            fs0 += __shfl_xor_sync(0xffffffffu, fs0, 1);
            fs0 += __shfl_xor_sync(0xffffffffu, fs0, 2);
            fs1 += __shfl_xor_sync(0xffffffffu, fs1, 1);
            fs1 += __shfl_xor_sync(0xffffffffu, fs1, 2);
            if ((lane & 3) == 0) {
                int row = un0 + wid * 16 + (lane >> 2);
                atomicAdd(&out[ub * NPn + row],     fs0);
                atomicAdd(&out[ub * NPn + row + 8], fs1);
            }
        }
    }
    #undef ISSUE
}

// ---------------------------------------------------------------------------
// kernel_launch
// Inputs: x, weights, xopt, R, group_indices, valid_mask, group_counts
// ---------------------------------------------------------------------------
extern "C" void kernel_launch(void* const* d_in, const int* in_sizes, int n_in,
                              void* d_out, int out_size)
{
    const float* x      = (const float*)d_in[0];
    const float* w      = (const float*)d_in[1];
    const float* xopt   = (const float*)d_in[2];
    const float* R      = (const float*)d_in[3];
    const int*   gidx   = (const int*)d_in[4];
    const void*  vmask  = (const void*)d_in[5];
    const int*   gc     = (const int*)d_in[6];
    float*       out    = (float*)d_out;

    cudaFuncSetAttribute(fitness_kernel,
                         cudaFuncAttributeMaxDynamicSharedMemorySize, SMEMB);

    dim3 tg(NPn / 32, Dn / 32, Bn);
    prep_kernel<<<tg, dim3(32, 8)>>>(x, xopt, gc, vmask, w, R, out);

    fitness_kernel<<<GRID, 256, SMEMB>>>(gidx, out);
}

// round 16
// speedup vs baseline: 1.0533x; 1.0533x over previous
#include <cuda_runtime.h>
#include <cuda_bf16.h>

#define Bn 8
#define Dn 1024
#define Gn 32
#define Kn 64
#define NPn 1024
#define NTILE 128
#define GRID 592      // 148 SMs * 4 CTA/SM, one wave

// Scratch (device globals; no allocation allowed)
__device__ unsigned int g_zh[(size_t)Bn * Dn * NPn / 2]; // z bf16 hi, [b][d][n] pairs
__device__ unsigned int g_zl[(size_t)Bn * Dn * NPn / 2]; // z bf16 lo (residual)
__device__ float        g_cw[Bn * Gn * Kn];              // coeff*mask*weight
__device__ unsigned int g_RT[2 * 2048];                  // R^T bf16 hi|lo, SW128-preswizzled
__device__ int          g_items[Bn * Gn];
__device__ int          g_nitems;

#define SWZ(o) ((o) ^ (((o) >> 3) & 0x70))

// pack two f32 -> bf16x2 (lo half = first arg), round-to-nearest
#define CVT2(res, lo, hi) \
    asm("cvt.rn.bf16x2.f32 %0, %1, %2;" : "=r"(res) : "f"(hi), "f"(lo))

#define CP_ASYNC16(dst_s32, src_g) \
    asm volatile("cp.async.cg.shared.global [%0], [%1], 16;" \
                 :: "r"(dst_s32), "l"(src_g))
#define CP_COMMIT() asm volatile("cp.async.commit_group;")
#define CP_WAIT0()  asm volatile("cp.async.wait_group 0;")

__device__ __forceinline__ unsigned int smem_u32(const void* p) {
    unsigned int a;
    asm("{ .reg .u64 t; cvta.to.shared.u64 t, %1; cvt.u32.u64 %0, t; }"
        : "=r"(a) : "l"(p));
    return a;
}

#define LDSM4(r, addr) \
    asm volatile("ldmatrix.sync.aligned.m8n8.x4.shared.b16 {%0,%1,%2,%3}, [%4];" \
        : "=r"((r)[0]), "=r"((r)[1]), "=r"((r)[2]), "=r"((r)[3]) : "r"(addr))
#define LDSM4T(r, addr) \
    asm volatile("ldmatrix.sync.aligned.m8n8.x4.trans.shared.b16 {%0,%1,%2,%3}, [%4];" \
        : "=r"((r)[0]), "=r"((r)[1]), "=r"((r)[2]), "=r"((r)[3]) : "r"(addr))

#define MMA16816(d, a, b0, b1) \
    asm volatile("mma.sync.aligned.m16n8k16.row.col.f32.bf16.bf16.f32 " \
        "{%0,%1,%2,%3}, {%4,%5,%6,%7}, {%8,%9}, {%0,%1,%2,%3};" \
        : "+f"((d)[0]), "+f"((d)[1]), "+f"((d)[2]), "+f"((d)[3]) \
        : "r"((a)[0]), "r"((a)[1]), "r"((a)[2]), "r"((a)[3]), \
          "r"(b0), "r"(b1))

// smem layout (dynamic; bases 1024-aligned for the swizzles)
#define SB1   0         // B r1: 64 x 64 bf16 (8 KB), SW128-preswizzled
#define SB2   8192      // B r2
#define SA    16384     // A bufs: 2 x (hi 8KB + lo 8KB), k-major 256B rows
#define SCW   49152     // 64 floats
#define SMEMB 49408

// ---------------------------------------------------------------------------
// Kernel 1 (prep): transpose + bf16 hi/lo split of z + cw + work list + R^T.
// ---------------------------------------------------------------------------
__global__ void prep_kernel(const float* __restrict__ x,
                            const float* __restrict__ xopt,
                            const int*   __restrict__ gc,
                            const void*  __restrict__ vm,
                            const float* __restrict__ w,
                            const float* __restrict__ R,
                            float*       __restrict__ out)
{
    __shared__ float t[32][33];     // [n_local][d_local]
    int b  = blockIdx.z;
    int n0 = blockIdx.x * 32;
    int d0 = blockIdx.y * 32;
    int tx = threadIdx.x, ty = threadIdx.y;
    int tid = ty * 32 + tx;

    #pragma unroll
    for (int j = ty; j < 32; j += 8) {
        int n = n0 + j, d = d0 + tx;
        t[j][tx] = x[((size_t)b * NPn + n) * Dn + d] - xopt[b * Dn + d];
    }
    __syncthreads();

    // write split bf16 planes: 16 lanes per d-row, each packs an n-pair
    #pragma unroll
    for (int it = 0; it < 2; ++it) {
        int dr = (tid >> 4) + it * 16;      // d_local 0..31
        int p  = tid & 15;                  // n-pair index
        float v0 = t[2 * p][dr];
        float v1 = t[2 * p + 1][dr];
        unsigned int hp; CVT2(hp, v0, v1);
        float v0r = v0 - __uint_as_float(hp << 16);
        float v1r = v1 - __uint_as_float(hp & 0xffff0000u);
        unsigned int lp; CVT2(lp, v0r, v1r);
        size_t o = (size_t)(b * Dn + d0 + dr) * (NPn / 2) + (n0 >> 1) + p;
        g_zh[o] = hp;
        g_zl[o] = lp;
    }

    if (blockIdx.x == 0 && blockIdx.y == 0) {
        int mode4 = 1;
        #pragma unroll
        for (int i = 0; i < 16; ++i) {
            unsigned int v = __ldg((const unsigned int*)vm + i);
            if (v != 0u && v != 1u && v != 0x3F800000u) mode4 = 0;
        }
        int gcb = gc[b];
        for (int i = tid; i < Gn * Kn; i += 256) {
            int g = i >> 6, k = i & 63;
            int gi = b * Gn * Kn + i;
            bool m;
            if (mode4) m = (((const unsigned int*)vm)[gi] != 0u);
            else       m = (((const unsigned char*)vm)[gi] != 0);
            float cf = exp2f((float)k * (19.931568569324174f / 63.0f));
            float wv = (g < gcb) ? w[b * Gn + g] : 0.0f;
            g_cw[gi] = m ? cf * wv : 0.0f;
        }
        for (int i = tid; i < NPn; i += 256) out[b * NPn + i] = 0.0f;

        if (b == 0) {
            if (tid == 0) {
                int mcnt = 0;
                for (int bb = 0; bb < Bn; ++bb) {
                    int c = gc[bb];
                    for (int g = 0; g < c; ++g) g_items[mcnt++] = (bb << 8) | g;
                }
                g_nitems = mcnt;
            }
            // R^T bf16 hi/lo split, SW128-pre-swizzled rows of 128 B (row = l)
            for (int i = tid; i < 2048; i += 256) {
                int l = i >> 5, p = i & 31, k0 = 2 * p;
                float v0 = R[k0 * Kn + l];
                float v1 = R[(k0 + 1) * Kn + l];
                unsigned int r1p; CVT2(r1p, v0, v1);
                float v0r = v0 - __uint_as_float(r1p << 16);
                float v1r = v1 - __uint_as_float(r1p & 0xffff0000u);
                unsigned int r2p; CVT2(r2p, v0r, v1r);
                int off = l * 128 + 4 * p;
                int sw  = SWZ(off) >> 2;
                g_RT[sw]        = r1p;
                g_RT[2048 + sw] = r2p;
            }
        }
    }
}

// ---------------------------------------------------------------------------
// Kernel 2: fitness via mma.sync bf16. Grid GRID=592 (one wave), block 256.
// Unit = ((b,g) item, 128-n tile); stage = 32-k half. cp.async gathers the
// pre-split bf16 A tile k-major (256B rows, ^((k&7)<<4) swizzle), double-
// buffered, one barrier per stage. A frags via ldmatrix.x4.trans, B via
// LDSM4. D = z1r1 + z1r2 + z2r1, fp32 reg accum.
// MMA order: l-tile PAIRS with 4-accumulator round-robin (chain distance 4)
// to unclog the tensor-pipe dependency serialization seen in R15.
// ---------------------------------------------------------------------------
__global__ __launch_bounds__(256, 4) void fitness_kernel(
    const int* __restrict__ gidx,
    float*     __restrict__ out)
{
    extern __shared__ char sm[];
    unsigned int smb = smem_u32(sm);
    int tid  = threadIdx.x;
    int wid  = tid >> 5;
    int lane = tid & 31;
    int cta  = blockIdx.x;

    int nunits = 8 * g_nitems;
    int mu = (cta < nunits) ? ((nunits - 1 - cta) / GRID + 1) : 0;
    if (mu == 0) return;
    int ts = 2 * mu;

    float* cw_s = (float*)(sm + SCW);

    // B tiles (r1|r2, 16 KB, pre-swizzled) -> smem once (lands with stage 0)
    {
        const char* src = (const char*)g_RT;
        for (int i = tid; i < 1024; i += 256)
            CP_ASYNC16(smb + SB1 + i * 16, src + i * 16);
    }

    // ---- per-lane ldmatrix address components ----
    int L8   = lane & 7;
    int tsel = lane >> 3;
    // A (trans, k-major rows of 256B): tile r0=(m0-7,k0-7) r1=(m8-15,k0-7)
    //                                  r2=(m0-7,k8-15) r3=(m8-15,k8-15)
    int a_kin  = L8 + ((tsel >> 1) << 3);              // k row within kstep
    int a_nseg = wid * 16 + ((tsel & 1) << 3);         // n segment
    unsigned int aoff = (unsigned)a_kin * 256 +
                        (((unsigned)(a_nseg * 2)) ^ ((unsigned)L8 << 4));
    // B (non-trans, l-major rows of 128B): r0,r1 = lt_even (k0-7 | k8-15),
    //                                      r2,r3 = lt_odd
    int b_kh  = (lane >> 3) & 1;                       // +8 k
    int b_lth = lane >> 4;                             // l tile within pair
    unsigned int b_row = (unsigned)(b_lth * 8 + L8) * 128;
    unsigned int b_kb0 = (unsigned)(b_kh * 16);
    unsigned int b_xor = (unsigned)L8 << 4;

    // gather: thread owns k_local = tid>>3 (0..31), 32B n-chunk (tid&7)
    int kq = tid >> 3;
    int c8 = tid & 7;
    unsigned int asw = ((unsigned)(c8 * 32)) ^ (((unsigned)kq & 7) << 4);
    unsigned int asw1 = ((unsigned)(c8 * 32 + 16)) ^ (((unsigned)kq & 7) << 4);

    // stage j: unit = cta + (j>>1)*GRID, k-half h = j&1
    #define ISSUE(j)                                                           \
    {                                                                          \
        int u_  = cta + ((j) >> 1) * GRID;                                     \
        int it_ = g_items[u_ >> 3];                                            \
        int b_  = it_ >> 8, g_ = it_ & 255, n0_ = (u_ & 7) * NTILE;            \
        int col_ = __ldg(gidx + (b_ * Gn + g_) * Kn + ((j) & 1) * 32 + kq);    \
        size_t so_ = ((size_t)(b_ * Dn + col_) * NPn + n0_) * 2 + c8 * 32;     \
        unsigned int ab_ = smb + SA + ((j) & 1) * 16384 + kq * 256;            \
        CP_ASYNC16(ab_ + asw,         (const char*)g_zh + so_);                \
        CP_ASYNC16(ab_ + asw1,        (const char*)g_zh + so_ + 16);           \
        CP_ASYNC16(ab_ + 8192 + asw,  (const char*)g_zl + so_);                \
        CP_ASYNC16(ab_ + 8192 + asw1, (const char*)g_zl + so_ + 16);           \
        CP_COMMIT();                                                           \
    }

    float d[8][4];
    int ub = 0, un0 = 0, ug = 0;

    ISSUE(0);

    for (int j = 0; j < ts; ++j) {
        int h = j & 1;

        CP_WAIT0();          // stage j (and B, on j=0) landed
        __syncthreads();     // visible to all; all past compute(j-1)
        if (j + 1 < ts) ISSUE(j + 1);

        if (h == 0) {
            int u  = cta + (j >> 1) * GRID;
            int it = g_items[u >> 3];
            ub = it >> 8; ug = it & 255; un0 = (u & 7) * NTILE;
            if (tid < Kn)
                cw_s[tid] = __ldg(g_cw + (ub * Gn + ug) * Kn + tid);
            #pragma unroll
            for (int lt = 0; lt < 8; ++lt)
                #pragma unroll
                for (int q = 0; q < 4; ++q) d[lt][q] = 0.0f;
        }

        unsigned int abuf = smb + SA + (unsigned)h * 16384;
        unsigned int hk64 = (unsigned)h * 64;

        #pragma unroll
        for (int ks = 0; ks < 2; ++ks) {
            unsigned int ah[4], al[4];
            LDSM4T(ah, abuf + ks * 4096 + aoff);
            LDSM4T(al, abuf + 8192 + ks * 4096 + aoff);
            unsigned int bko = (hk64 + (unsigned)(ks * 32) + b_kb0) ^ b_xor;
            #pragma unroll
            for (int lpp = 0; lpp < 2; ++lpp) {
                // B addresses for adjacent lp pair (l-tiles 4lpp..4lpp+3)
                unsigned int bb0 = (unsigned)(2 * lpp)     * 2048 + b_row + bko;
                unsigned int bb1 = (unsigned)(2 * lpp + 1) * 2048 + b_row + bko;
                unsigned int bh0[4], bh1[4], bl0[4], bl1[4];
                LDSM4(bh0, smb + SB1 + bb0);
                LDSM4(bh1, smb + SB1 + bb1);
                float* d0 = d[4 * lpp + 0];
                float* d1 = d[4 * lpp + 1];
                float* d2 = d[4 * lpp + 2];
                float* d3 = d[4 * lpp + 3];
                // round-robin over 4 independent accumulators (distance 4)
                MMA16816(d0, ah, bh0[0], bh0[1]);
                MMA16816(d1, ah, bh0[2], bh0[3]);
                MMA16816(d2, ah, bh1[0], bh1[1]);
                MMA16816(d3, ah, bh1[2], bh1[3]);
                MMA16816(d0, al, bh0[0], bh0[1]);
                MMA16816(d1, al, bh0[2], bh0[3]);
                MMA16816(d2, al, bh1[0], bh1[1]);
                MMA16816(d3, al, bh1[2], bh1[3]);
                LDSM4(bl0, smb + SB2 + bb0);
                LDSM4(bl1, smb + SB2 + bb1);
                MMA16816(d0, ah, bl0[0], bl0[1]);
                MMA16816(d1, ah, bl0[2], bl0[3]);
                MMA16816(d2, ah, bl1[0], bl1[1]);
                MMA16816(d3, ah, bl1[2], bl1[3]);
            }
        }

        if (h == 1) {
            // epilogue: D rows wid*16 + lane>>2 (+8); cols lt*8+(lane&3)*2+{0,1}
            float fs0 = 0.0f, fs1 = 0.0f;
            #pragma unroll
            for (int lt = 0; lt < 8; ++lt) {
                int c0 = lt * 8 + (lane & 3) * 2;
                float cw0 = cw_s[c0], cw1 = cw_s[c0 + 1];
                fs0 += cw0 * d[lt][0] * d[lt][0] + cw1 * d[lt][1] * d[lt][1];
                fs1 += cw0 * d[lt][2] * d[lt][2] + cw1 * d[lt][3] * d[lt][3];
            }
            fs0 += __shfl_xor_sync(0xffffffffu, fs0, 1);
            fs0 += __shfl_xor_sync(0xffffffffu, fs0, 2);
            fs1 += __shfl_xor_sync(0xffffffffu, fs1, 1);
            fs1 += __shfl_xor_sync(0xffffffffu, fs1, 2);
            if ((lane & 3) == 0) {
                int row = un0 + wid * 16 + (lane >> 2);
                atomicAdd(&out[ub * NPn + row],     fs0);
                atomicAdd(&out[ub * NPn + row + 8], fs1);
            }
        }
    }
    #undef ISSUE
}

// ---------------------------------------------------------------------------
// kernel_launch
// Inputs: x, weights, xopt, R, group_indices, valid_mask, group_counts
// ---------------------------------------------------------------------------
extern "C" void kernel_launch(void* const* d_in, const int* in_sizes, int n_in,
                              void* d_out, int out_size)
{
    const float* x      = (const float*)d_in[0];
    const float* w      = (const float*)d_in[1];
    const float* xopt   = (const float*)d_in[2];
    const float* R      = (const float*)d_in[3];
    const int*   gidx   = (const int*)d_in[4];
    const void*  vmask  = (const void*)d_in[5];
    const int*   gc     = (const int*)d_in[6];
    float*       out    = (float*)d_out;

    cudaFuncSetAttribute(fitness_kernel,
                         cudaFuncAttributeMaxDynamicSharedMemorySize, SMEMB);

    dim3 tg(NPn / 32, Dn / 32, Bn);
    prep_kernel<<<tg, dim3(32, 8)>>>(x, xopt, gc, vmask, w, R, out);

    fitness_kernel<<<GRID, 256, SMEMB>>>(gidx, out);
}